// round 15
// baseline (speedup 1.0000x reference)
#include <cuda_runtime.h>
#include <cuda_bf16.h>

// Forward-fill (LOCF) over x:(B=32, L=4096, N=256) fp32, NaN = missing.
// Persistent grid-stride variant of the R11/R14 design: 1024 CTAs x 128 thr,
// each CTA processes 4 chunks (bid = blockIdx.x + pass*1024) -> ~1 wave,
// removing 3 wave transitions + the 544-CTA ragged tail of the 4096-CTA grid.
//
// Per chunk (unchanged, measured 60.4us @ 5.75 TB/s):
//   thread = channel pair (float2): 32 front-batched LDG.64 (256B in flight).
//   combined scan + store (register-fed; unresolved prefix gets NaN);
//   ~20% of channels walk x backwards for the carry (E = 1.25 loads), patch.

#define BB 32
#define LL 4096
#define NN 256
#define LC 32
#define CC (LL / LC)          // 128 chunks per batch
#define NCHUNK (BB * CC)      // 4096 chunks
#define N2 (NN / 2)           // 128 float2 channels -> block size
#define GRID 1024
#define PASSES (NCHUNK / GRID) // 4

// Backward walk: last observation in this channel at step <= l0. 0.0f if none.
static __device__ __forceinline__ float walk_back(const float* __restrict__ xrow,
                                                  int l0) {
    for (int l = l0; l >= 0; l--) {
        float v = __ldg(xrow + (size_t)l * NN);
        if (v == v) return v;
    }
    return 0.0f;
}

template <bool WRITE_MASK>
__global__ void __launch_bounds__(128) k_locf(const float2* __restrict__ x,
                                              float2* __restrict__ out,
                                              float2* __restrict__ outm) {
    const int t = threadIdx.x;            // channel pair (channels 2t, 2t+1)

    #pragma unroll 1
    for (int pass = 0; pass < PASSES; pass++) {
        const int bid = blockIdx.x + pass * GRID;   // (b, c)
        const int c   = bid % CC;
        const int b   = bid / CC;

        const size_t base = ((size_t)b * LL + (size_t)c * LC) * N2 + t;

        // ---- phase 1: 32 independent LDG.64 (256 bytes in flight)
        float2 v[LC];
        #pragma unroll
        for (int l = 0; l < LC; l++)
            v[l] = __ldcs(x + base + (size_t)l * N2);

        // ---- phase 2: combined scan + store (prefix = NaN, patched below)
        float sx = __int_as_float(0x7fc00000), sy = sx;
        int fx = 0, fy = 0;
        #pragma unroll
        for (int l = 0; l < LC; l++) {
            bool vx = (v[l].x == v[l].x), vy = (v[l].y == v[l].y);
            sx = vx ? v[l].x : sx;
            sy = vy ? v[l].y : sy;
            fx = (sx == sx) ? fx : (l + 1);
            fy = (sy == sy) ? fy : (l + 1);
            __stcs(out + base + (size_t)l * N2, make_float2(sx, sy));
            if (WRITE_MASK)
                __stcs(outm + base + (size_t)l * N2,
                       make_float2(vx ? 1.0f : 0.0f, vy ? 1.0f : 0.0f));
        }

        // ---- phase 3: carry via backward walk through x, patch the prefix
        if (fx > 0 || fy > 0) {
            float cx = 0.0f, cy = 0.0f;
            if (c > 0) {
                const float* xs = (const float*)x + (size_t)b * LL * NN;
                const int l0 = c * LC - 1;
                if (fx > 0) cx = walk_back(xs + 2 * t, l0);
                if (fy > 0) cy = walk_back(xs + 2 * t + 1, l0);
            }
            float* o = (float*)out;
            const size_t sbase = 2 * base;    // scalar index of channel 2t
            for (int l = 0; l < fx; l++)
                __stcs(o + sbase + (size_t)l * NN, cx);
            for (int l = 0; l < fy; l++)
                __stcs(o + sbase + 1 + (size_t)l * NN, cy);
        }
    }
}

extern "C" void kernel_launch(void* const* d_in, const int* in_sizes, int n_in,
                              void* d_out, int out_size) {
    const float2* x = (const float2*)d_in[0];
    long long total = (long long)in_sizes[0];   // 33554432
    float* out = (float*)d_out;

    if ((long long)out_size >= 2 * total) {
        k_locf<true><<<GRID, N2>>>(x, (float2*)out, (float2*)(out + total));
    } else {
        k_locf<false><<<GRID, N2>>>(x, (float2*)out, nullptr);
    }
}

// round 17
// speedup vs baseline: 1.1730x; 1.1730x over previous
#include <cuda_runtime.h>
#include <cuda_bf16.h>

// Forward-fill (LOCF) over x:(B=32, L=4096, N=256) fp32, NaN = missing.
// FINAL kernel (R11/R14 design, twice measured at 64.0/64.3 us total;
// main kernel 60.4-61.1 us @ 5.67-5.75 TB/s = achieved GB300 ceiling for
// this 1-read/2-write stream at NAT clocks).
//
//   chunk = 32 steps; grid = B*(L/32) = 4096 CTAs x 128 threads.
//   thread = channel pair (float2): 32 front-batched LDG.64 (256B in flight).
//   Phase 1: batch-load 32 steps into regs (full MLP; coalesced rows).
//   Phase 2: combined scan + store (stores register-fed; unresolved prefix
//            gets NaN and is patched in phase 3).
//   Phase 3: ~20% of channels walk x backwards for the carry
//            (E[walk] = 1.25 loads, P(walk > k) = 0.2^k, L2-likely), patch.
//
// Search closed (rounds 3-15): chunk {16,64,256}, scalar/float4 widths,
// publication-array protocols, persistent grids -- all equal or worse.

#define BB 32
#define LL 4096
#define NN 256
#define LC 32
#define CC (LL / LC)          // 128 chunks per batch
#define NCHUNK (BB * CC)      // 4096 CTAs
#define N2 (NN / 2)           // 128 float2 channels -> block size

// Backward walk: last observation in this channel at step <= l0. 0.0f if none.
static __device__ __forceinline__ float walk_back(const float* __restrict__ xrow,
                                                  int l0) {
    for (int l = l0; l >= 0; l--) {
        float v = __ldg(xrow + (size_t)l * NN);
        if (v == v) return v;
    }
    return 0.0f;
}

template <bool WRITE_MASK>
__global__ void __launch_bounds__(128) k_locf(const float2* __restrict__ x,
                                              float2* __restrict__ out,
                                              float2* __restrict__ outm) {
    const int t   = threadIdx.x;          // channel pair (channels 2t, 2t+1)
    const int bid = blockIdx.x;           // (b, c)
    const int c   = bid % CC;
    const int b   = bid / CC;

    const size_t base = ((size_t)b * LL + (size_t)c * LC) * N2 + t;

    // ---- phase 1: 32 independent LDG.64 (256 bytes in flight per thread)
    float2 v[LC];
    #pragma unroll
    for (int l = 0; l < LC; l++)
        v[l] = __ldcs(x + base + (size_t)l * N2);

    // ---- phase 2: combined scan + store (register-fed stores; prefix = NaN)
    float sx = __int_as_float(0x7fc00000), sy = sx;
    int fx = 0, fy = 0;
    #pragma unroll
    for (int l = 0; l < LC; l++) {
        bool vx = (v[l].x == v[l].x), vy = (v[l].y == v[l].y);
        sx = vx ? v[l].x : sx;
        sy = vy ? v[l].y : sy;
        fx = (sx == sx) ? fx : (l + 1);
        fy = (sy == sy) ? fy : (l + 1);
        __stcs(out + base + (size_t)l * N2, make_float2(sx, sy));
        if (WRITE_MASK)
            __stcs(outm + base + (size_t)l * N2,
                   make_float2(vx ? 1.0f : 0.0f, vy ? 1.0f : 0.0f));
    }

    // ---- phase 3: carry via backward walk through x, then patch the prefix
    if (fx > 0 || fy > 0) {
        float cx = 0.0f, cy = 0.0f;
        if (c > 0) {
            const float* xs = (const float*)x + (size_t)b * LL * NN;
            const int l0 = c * LC - 1;
            if (fx > 0) cx = walk_back(xs + 2 * t, l0);
            if (fy > 0) cy = walk_back(xs + 2 * t + 1, l0);
        }
        float* o = (float*)out;
        const size_t sbase = 2 * base;    // scalar index of channel 2t
        for (int l = 0; l < fx; l++)
            __stcs(o + sbase + (size_t)l * NN, cx);
        for (int l = 0; l < fy; l++)
            __stcs(o + sbase + 1 + (size_t)l * NN, cy);
    }
}

extern "C" void kernel_launch(void* const* d_in, const int* in_sizes, int n_in,
                              void* d_out, int out_size) {
    const float2* x = (const float2*)d_in[0];
    long long total = (long long)in_sizes[0];   // 33554432
    float* out = (float*)d_out;

    if ((long long)out_size >= 2 * total) {
        k_locf<true><<<NCHUNK, N2>>>(x, (float2*)out, (float2*)(out + total));
    } else {
        k_locf<false><<<NCHUNK, N2>>>(x, (float2*)out, nullptr);
    }
}